// round 4
// baseline (speedup 1.0000x reference)
#include <cuda_runtime.h>
#include <math.h>

#define VIEWS 8
#define SEQL  2048
#define HID   1024
#define ATT   128
#define SCALE 0.08838834764831845f   /* 1/sqrt(128) */

// ---------------- scratch (device globals: no allocations allowed) ----------
__device__ float g_qh[VIEWS * SEQL * ATT];
__device__ float g_kh[VIEWS * SEQL * ATT];
__device__ float g_vh[VIEWS * SEQL * ATT];
__device__ float g_x [SEQL * HID];          // x already transposed to [S, V*A]

// ============================================================================
// Generic 64x128 output-tile SGEMM: C = (A@B + bias) * mul
// A: [.., lda] row-major (pre-offset to tile row 0)
// B: [Ktot, ldb] row-major (pre-offset to tile col 0)
// 256 threads, micro-tile 4x8 per thread, BK=32.
// ============================================================================
__device__ __forceinline__ void sgemm_64x128(
    const float* __restrict__ A, int lda,
    const float* __restrict__ B, int ldb,
    const float* __restrict__ bias,
    float* __restrict__ C, int ldc,
    int Ktot, float mul)
{
    __shared__ float As[32][65];    // transposed: As[k][m]
    __shared__ float Bs[32][132];   // Bs[k][n]

    const int tid = threadIdx.x;
    const int ty  = tid >> 4;       // 0..15 -> rows ty*4..ty*4+3
    const int tx  = tid & 15;       // 0..15 -> cols {tx*4..+3, 64+tx*4..+3}

    float acc[4][8];
#pragma unroll
    for (int i = 0; i < 4; i++)
#pragma unroll
        for (int j = 0; j < 8; j++) acc[i][j] = 0.f;

    for (int k0 = 0; k0 < Ktot; k0 += 32) {
        // load A tile 64x32 (transposed into smem)
#pragma unroll
        for (int i = 0; i < 2; i++) {
            const int r  = (tid >> 3) + i * 32;
            const int c4 = (tid & 7) * 4;
            const float4 t = *(const float4*)&A[(size_t)r * lda + k0 + c4];
            As[c4 + 0][r] = t.x; As[c4 + 1][r] = t.y;
            As[c4 + 2][r] = t.z; As[c4 + 3][r] = t.w;
        }
        // load B tile 32x128
#pragma unroll
        for (int i = 0; i < 4; i++) {
            const int r  = (tid >> 5) + i * 8;
            const int c4 = (tid & 31) * 4;
            *(float4*)&Bs[r][c4] = *(const float4*)&B[(size_t)(k0 + r) * ldb + c4];
        }
        __syncthreads();

#pragma unroll
        for (int kk = 0; kk < 32; kk++) {
            float a[4];
#pragma unroll
            for (int i = 0; i < 4; i++) a[i] = As[kk][ty * 4 + i];
            const float4 b0 = *(const float4*)&Bs[kk][tx * 4];
            const float4 b1 = *(const float4*)&Bs[kk][tx * 4 + 64];
#pragma unroll
            for (int i = 0; i < 4; i++) {
                acc[i][0] += a[i] * b0.x;  acc[i][1] += a[i] * b0.y;
                acc[i][2] += a[i] * b0.z;  acc[i][3] += a[i] * b0.w;
                acc[i][4] += a[i] * b1.x;  acc[i][5] += a[i] * b1.y;
                acc[i][6] += a[i] * b1.z;  acc[i][7] += a[i] * b1.w;
            }
        }
        __syncthreads();
    }

    const float4 bb0 = *(const float4*)&bias[tx * 4];
    const float4 bb1 = *(const float4*)&bias[tx * 4 + 64];
#pragma unroll
    for (int i = 0; i < 4; i++) {
        float4 o0, o1;
        o0.x = (acc[i][0] + bb0.x) * mul;  o0.y = (acc[i][1] + bb0.y) * mul;
        o0.z = (acc[i][2] + bb0.z) * mul;  o0.w = (acc[i][3] + bb0.w) * mul;
        o1.x = (acc[i][4] + bb1.x) * mul;  o1.y = (acc[i][5] + bb1.y) * mul;
        o1.z = (acc[i][6] + bb1.z) * mul;  o1.w = (acc[i][7] + bb1.w) * mul;
        *(float4*)&C[(size_t)(ty * 4 + i) * ldc + tx * 4]      = o0;
        *(float4*)&C[(size_t)(ty * 4 + i) * ldc + tx * 4 + 64] = o1;
    }
}

// ---------------------------------------------------------------------------
// Kernel 1: fused QKV projection.  grid (32 Mtiles, 8 views, 3 proj)
// ---------------------------------------------------------------------------
__global__ void __launch_bounds__(256) proj_kernel(
    const float* __restrict__ q, const float* __restrict__ k,
    const float* __restrict__ v,
    const float* __restrict__ wq, const float* __restrict__ bq,
    const float* __restrict__ wk, const float* __restrict__ bk,
    const float* __restrict__ wv, const float* __restrict__ bv)
{
    const int view = blockIdx.y;
    const int pz   = blockIdx.z;
    const float *A, *W, *bias;
    float* O;
    float mul = 1.0f;
    if (pz == 0)      { A = q; W = wq; bias = bq; O = g_qh; mul = SCALE; }
    else if (pz == 1) { A = k; W = wk; bias = bk; O = g_kh; }
    else              { A = v; W = wv; bias = bv; O = g_vh; }

    A += (size_t)view * SEQL * HID;
    O += (size_t)view * SEQL * ATT;
    const int row0 = blockIdx.x * 64;
    sgemm_64x128(A + (size_t)row0 * HID, HID, W, ATT, bias,
                 O + (size_t)row0 * ATT, ATT, HID, mul);
}

// ---------------------------------------------------------------------------
// Kernel 2: fused attention.  grid (32 q-tiles, 8 views), 256 threads.
//   streams 64-row K/V/bias tiles; two accumulators:
//     soft = online-softmax(QK^T) @ V   (rescaled, normalized at the end)
//     bacc = attn_bias @ V              (plain accumulation)
//   x = soft/l + bacc, stored transposed into g_x[S][V*A].
// ---------------------------------------------------------------------------
#define QS  132           // padded row stride for 128-wide tiles
#define SS  68            // padded row stride for 64-wide tiles
#define SMEM_ATTN_BYTES ((3 * 64 * QS + 2 * 64 * SS + 3 * 64) * 4)

__global__ void __launch_bounds__(256) attn_kernel(const float* __restrict__ attn_bias)
{
    extern __shared__ float sm[];
    float* Qs   = sm;
    float* Ks   = Qs  + 64 * QS;
    float* Vs   = Ks  + 64 * QS;
    float* Ssm  = Vs  + 64 * QS;
    float* Bsm  = Ssm + 64 * SS;
    float* mrow = Bsm + 64 * SS;
    float* lrow = mrow + 64;
    float* crow = lrow + 64;

    const int tid  = threadIdx.x;
    const int view = blockIdx.y;
    const int q0   = blockIdx.x * 64;

    const float* qh = g_qh + (size_t)view * SEQL * ATT;
    const float* kh = g_kh + (size_t)view * SEQL * ATT;
    const float* vh = g_vh + (size_t)view * SEQL * ATT;
    const float* ab = attn_bias + (size_t)view * SEQL * SEQL + (size_t)q0 * SEQL;

    // load Q tile (64x128) once
    for (int i = tid; i < 64 * 32; i += 256) {
        const int r = i >> 5, c4 = (i & 31) << 2;
        *(float4*)&Qs[r * QS + c4] = *(const float4*)&qh[(size_t)(q0 + r) * ATT + c4];
    }
    if (tid < 64) { mrow[tid] = -3.0e38f; lrow[tid] = 0.f; }

    // per-thread output ownership: 2 rows x 16 dims
    const int rp = tid >> 3;            // 0..31
    const int r0 = rp * 2;
    const int d0 = (tid & 7) * 16;
    float as0[16], as1[16], ab0[16], ab1[16];
#pragma unroll
    for (int i = 0; i < 16; i++) { as0[i] = as1[i] = ab0[i] = ab1[i] = 0.f; }

    const int ty = tid >> 4, tx = tid & 15;   // S-compute layout

    __syncthreads();

    for (int kt = 0; kt < SEQL / 64; kt++) {
        // ---- load K, V, bias tiles ----
        const float* kbase = kh + (size_t)(kt * 64) * ATT;
        const float* vbase = vh + (size_t)(kt * 64) * ATT;
        for (int i = tid; i < 64 * 32; i += 256) {
            const int r = i >> 5, c4 = (i & 31) << 2;
            *(float4*)&Ks[r * QS + c4] = *(const float4*)&kbase[(size_t)r * ATT + c4];
            *(float4*)&Vs[r * QS + c4] = *(const float4*)&vbase[(size_t)r * ATT + c4];
        }
        for (int i = tid; i < 64 * 16; i += 256) {
            const int r = i >> 4, c4 = (i & 15) << 2;
            *(float4*)&Bsm[r * SS + c4] = *(const float4*)&ab[(size_t)r * SEQL + kt * 64 + c4];
        }
        __syncthreads();

        // ---- phase 1: S = Q @ K^T (rows ty*4.., cols tx + j*16) ----
        {
            float s[4][4];
#pragma unroll
            for (int i = 0; i < 4; i++)
#pragma unroll
                for (int j = 0; j < 4; j++) s[i][j] = 0.f;

            for (int kk = 0; kk < 128; kk += 4) {
                float4 a[4], b[4];
#pragma unroll
                for (int i = 0; i < 4; i++) a[i] = *(const float4*)&Qs[(ty * 4 + i) * QS + kk];
#pragma unroll
                for (int j = 0; j < 4; j++) b[j] = *(const float4*)&Ks[(tx + j * 16) * QS + kk];
#pragma unroll
                for (int i = 0; i < 4; i++)
#pragma unroll
                    for (int j = 0; j < 4; j++)
                        s[i][j] += a[i].x * b[j].x + a[i].y * b[j].y
                                 + a[i].z * b[j].z + a[i].w * b[j].w;
            }
#pragma unroll
            for (int i = 0; i < 4; i++)
#pragma unroll
                for (int j = 0; j < 4; j++)
                    Ssm[(ty * 4 + i) * SS + tx + j * 16] = s[i][j];
        }
        __syncthreads();

        // ---- phase 2: online softmax update (4 lanes per row) ----
        {
            const int row = tid >> 2, l4 = tid & 3, cb = l4 * 16;
            float lm = -3.0e38f;
#pragma unroll
            for (int c = 0; c < 16; c++) lm = fmaxf(lm, Ssm[row * SS + cb + c]);
            lm = fmaxf(lm, __shfl_xor_sync(0xffffffffu, lm, 1));
            lm = fmaxf(lm, __shfl_xor_sync(0xffffffffu, lm, 2));
            const float mold = mrow[row];
            const float mnew = fmaxf(mold, lm);
            float ls = 0.f;
#pragma unroll
            for (int c = 0; c < 16; c++) {
                const float e = __expf(Ssm[row * SS + cb + c] - mnew);
                Ssm[row * SS + cb + c] = e;
                ls += e;
            }
            ls += __shfl_xor_sync(0xffffffffu, ls, 1);
            ls += __shfl_xor_sync(0xffffffffu, ls, 2);
            if (l4 == 0) {
                const float corr = __expf(mold - mnew);
                crow[row] = corr;
                mrow[row] = mnew;
                lrow[row] = lrow[row] * corr + ls;
            }
        }
        __syncthreads();

        // ---- phase 3: acc_soft = acc_soft*corr + P@V ;  acc_bias += B@V ----
        {
            const float c0 = crow[r0], c1 = crow[r0 + 1];
#pragma unroll
            for (int i = 0; i < 16; i++) { as0[i] *= c0; as1[i] *= c1; }
#pragma unroll 4
            for (int kr = 0; kr < 64; kr++) {
                const float p0 = Ssm[r0 * SS + kr];
                const float p1 = Ssm[(r0 + 1) * SS + kr];
                const float b0 = Bsm[r0 * SS + kr];
                const float b1 = Bsm[(r0 + 1) * SS + kr];
                const float* vr = &Vs[kr * QS + d0];
#pragma unroll
                for (int u = 0; u < 4; u++) {
                    const float4 vv = *(const float4*)&vr[u * 4];
                    as0[u*4+0] += p0 * vv.x;  as0[u*4+1] += p0 * vv.y;
                    as0[u*4+2] += p0 * vv.z;  as0[u*4+3] += p0 * vv.w;
                    as1[u*4+0] += p1 * vv.x;  as1[u*4+1] += p1 * vv.y;
                    as1[u*4+2] += p1 * vv.z;  as1[u*4+3] += p1 * vv.w;
                    ab0[u*4+0] += b0 * vv.x;  ab0[u*4+1] += b0 * vv.y;
                    ab0[u*4+2] += b0 * vv.z;  ab0[u*4+3] += b0 * vv.w;
                    ab1[u*4+0] += b1 * vv.x;  ab1[u*4+1] += b1 * vv.y;
                    ab1[u*4+2] += b1 * vv.z;  ab1[u*4+3] += b1 * vv.w;
                }
            }
        }
        __syncthreads();
    }

    // ---- epilogue: x = soft/l + bias_acc, stored transposed [S, V*A] ----
    const float inv0 = 1.f / lrow[r0];
    const float inv1 = 1.f / lrow[r0 + 1];
    float* x0 = g_x + (size_t)(q0 + r0) * HID + view * ATT + d0;
    float* x1 = x0 + HID;
#pragma unroll
    for (int u = 0; u < 4; u++) {
        float4 o0, o1;
        o0.x = as0[u*4+0] * inv0 + ab0[u*4+0];
        o0.y = as0[u*4+1] * inv0 + ab0[u*4+1];
        o0.z = as0[u*4+2] * inv0 + ab0[u*4+2];
        o0.w = as0[u*4+3] * inv0 + ab0[u*4+3];
        o1.x = as1[u*4+0] * inv1 + ab1[u*4+0];
        o1.y = as1[u*4+1] * inv1 + ab1[u*4+1];
        o1.z = as1[u*4+2] * inv1 + ab1[u*4+2];
        o1.w = as1[u*4+3] * inv1 + ab1[u*4+3];
        *(float4*)&x0[u * 4] = o0;
        *(float4*)&x1[u * 4] = o1;
    }
}

// ---------------------------------------------------------------------------
// Kernel 3: out = x @ wo + bo.   grid (32 Mtiles, 8 Ntiles)
// ---------------------------------------------------------------------------
__global__ void __launch_bounds__(256) out_kernel(
    const float* __restrict__ wo, const float* __restrict__ bo,
    float* __restrict__ out)
{
    const int row0 = blockIdx.x * 64;
    const int col0 = blockIdx.y * 128;
    sgemm_64x128(g_x + (size_t)row0 * HID, HID,
                 wo + col0, HID, bo + col0,
                 out + (size_t)row0 * HID + col0, HID, HID, 1.0f);
}

// ---------------------------------------------------------------------------
extern "C" void kernel_launch(void* const* d_in, const int* in_sizes, int n_in,
                              void* d_out, int out_size)
{
    const float* q  = (const float*)d_in[0];
    const float* k  = (const float*)d_in[1];
    const float* v  = (const float*)d_in[2];
    const float* ab = (const float*)d_in[3];
    const float* wq = (const float*)d_in[4];
    const float* bq = (const float*)d_in[5];
    const float* wk = (const float*)d_in[6];
    const float* bk = (const float*)d_in[7];
    const float* wv = (const float*)d_in[8];
    const float* bv = (const float*)d_in[9];
    const float* wo = (const float*)d_in[10];
    const float* bo = (const float*)d_in[11];
    float* out = (float*)d_out;

    cudaFuncSetAttribute(attn_kernel, cudaFuncAttributeMaxDynamicSharedMemorySize,
                         SMEM_ATTN_BYTES);

    proj_kernel<<<dim3(SEQL / 64, VIEWS, 3), 256>>>(q, k, v, wq, bq, wk, bk, wv, bv);
    attn_kernel<<<dim3(SEQL / 64, VIEWS), 256, SMEM_ATTN_BYTES>>>(ab);
    out_kernel<<<dim3(SEQL / 64, HID / 128), 256>>>(wo, bo, out);
}

// round 5
// speedup vs baseline: 3.9455x; 3.9455x over previous
#include <cuda_runtime.h>
#include <math.h>
#include <stdint.h>

#define VIEWS 8
#define SEQL  2048
#define HID   1024
#define ATT   128
#define SCALE 0.08838834764831845f   /* 1/sqrt(128) */

// ---------------- scratch (device globals: no allocations allowed) ----------
__device__ float g_qh[VIEWS * SEQL * ATT];
__device__ float g_kh[VIEWS * SEQL * ATT];
__device__ float g_vh[VIEWS * SEQL * ATT];
__device__ float g_x [SEQL * HID];          // x already transposed to [S, V*A]

// ---------------------------------------------------------------------------
// TF32 helpers
// ---------------------------------------------------------------------------
__device__ __forceinline__ float tf32r(float x) {
    uint32_t u;
    asm("cvt.rna.tf32.f32 %0, %1;" : "=r"(u) : "f"(x));
    return __uint_as_float(u);
}
__device__ __forceinline__ float4 tf32r4(float4 t) {
    t.x = tf32r(t.x); t.y = tf32r(t.y); t.z = tf32r(t.z); t.w = tf32r(t.w);
    return t;
}

// d += A(16x8,row) * B(8x8,col)   tf32 inputs, fp32 accum
__device__ __forceinline__ void mma_tf32(float* d,
    uint32_t a0, uint32_t a1, uint32_t a2, uint32_t a3,
    uint32_t b0, uint32_t b1)
{
    asm volatile(
        "mma.sync.aligned.m16n8k8.row.col.f32.tf32.tf32.f32 "
        "{%0,%1,%2,%3},{%4,%5,%6,%7},{%8,%9},{%0,%1,%2,%3};\n"
        : "+f"(d[0]), "+f"(d[1]), "+f"(d[2]), "+f"(d[3])
        : "r"(a0), "r"(a1), "r"(a2), "r"(a3), "r"(b0), "r"(b1));
}

__device__ __forceinline__ uint32_t lduf(const float* p) {
    return __float_as_uint(*p);
}

// ============================================================================
// TF32 tensor-core SGEMM, 64x128 output tile, 256 threads (8 warps).
// C = (A@B + bias) * mul.   A:[..,lda] rm (pre-offset), B:[Ktot,ldb] rm.
// Warp tile: 16(m) x 64(n).  BK = 32.
// ============================================================================
#define GLDA 36     // As row stride (pad)
#define GLDB 136    // Bs row stride (pad)

__device__ __forceinline__ void sgemm_tf32_64x128(
    const float* __restrict__ A, int lda,
    const float* __restrict__ B, int ldb,
    const float* __restrict__ bias,
    float* __restrict__ C, int ldc,
    int Ktot, float mul)
{
    __shared__ float As[64 * GLDA];
    __shared__ float Bs[32 * GLDB];

    const int tid  = threadIdx.x;
    const int wid  = tid >> 5;
    const int lane = tid & 31;
    const int g    = lane >> 2;     // groupID
    const int tig  = lane & 3;      // thread in group

    const int m0 = (wid & 3) * 16;
    const int n0 = (wid >> 2) * 64;

    float acc[8][4];
#pragma unroll
    for (int nt = 0; nt < 8; nt++)
#pragma unroll
        for (int i = 0; i < 4; i++) acc[nt][i] = 0.f;

    for (int k0 = 0; k0 < Ktot; k0 += 32) {
        // A tile 64x32 (tf32-rounded)
#pragma unroll
        for (int i = 0; i < 2; i++) {
            const int r  = (tid >> 3) + i * 32;
            const int c4 = (tid & 7) * 4;
            float4 t = tf32r4(*(const float4*)&A[(size_t)r * lda + k0 + c4]);
            *(float4*)&As[r * GLDA + c4] = t;
        }
        // B tile 32x128 (tf32-rounded)
#pragma unroll
        for (int i = 0; i < 4; i++) {
            const int r  = (tid >> 5) + i * 8;
            const int c4 = (tid & 31) * 4;
            float4 t = tf32r4(*(const float4*)&B[(size_t)(k0 + r) * ldb + c4]);
            *(float4*)&Bs[r * GLDB + c4] = t;
        }
        __syncthreads();

#pragma unroll
        for (int kk = 0; kk < 32; kk += 8) {
            const uint32_t a0 = lduf(&As[(m0 + g)     * GLDA + kk + tig]);
            const uint32_t a1 = lduf(&As[(m0 + g + 8) * GLDA + kk + tig]);
            const uint32_t a2 = lduf(&As[(m0 + g)     * GLDA + kk + tig + 4]);
            const uint32_t a3 = lduf(&As[(m0 + g + 8) * GLDA + kk + tig + 4]);
#pragma unroll
            for (int nt = 0; nt < 8; nt++) {
                const int nc = n0 + nt * 8 + g;
                const uint32_t b0 = lduf(&Bs[(kk + tig)     * GLDB + nc]);
                const uint32_t b1 = lduf(&Bs[(kk + tig + 4) * GLDB + nc]);
                mma_tf32(acc[nt], a0, a1, a2, a3, b0, b1);
            }
        }
        __syncthreads();
    }

    // epilogue: pairs (c0,c1) at (m0+g, col), (c2,c3) at (m0+g+8, col)
#pragma unroll
    for (int nt = 0; nt < 8; nt++) {
        const int col = n0 + nt * 8 + tig * 2;
        const float b0 = bias[col], b1 = bias[col + 1];
        float2 o0, o1;
        o0.x = (acc[nt][0] + b0) * mul;  o0.y = (acc[nt][1] + b1) * mul;
        o1.x = (acc[nt][2] + b0) * mul;  o1.y = (acc[nt][3] + b1) * mul;
        *(float2*)&C[(size_t)(m0 + g)     * ldc + col] = o0;
        *(float2*)&C[(size_t)(m0 + g + 8) * ldc + col] = o1;
    }
}

// ---------------------------------------------------------------------------
// Kernel 1: fused QKV projection.  grid (32 Mtiles, 8 views, 3 proj)
// ---------------------------------------------------------------------------
__global__ void __launch_bounds__(256) proj_kernel(
    const float* __restrict__ q, const float* __restrict__ k,
    const float* __restrict__ v,
    const float* __restrict__ wq, const float* __restrict__ bq,
    const float* __restrict__ wk, const float* __restrict__ bk,
    const float* __restrict__ wv, const float* __restrict__ bv)
{
    const int view = blockIdx.y;
    const int pz   = blockIdx.z;
    const float *A, *W, *bias;
    float* O;
    float mul = 1.0f;
    if (pz == 0)      { A = q; W = wq; bias = bq; O = g_qh; mul = SCALE; }
    else if (pz == 1) { A = k; W = wk; bias = bk; O = g_kh; }
    else              { A = v; W = wv; bias = bv; O = g_vh; }

    A += (size_t)view * SEQL * HID;
    O += (size_t)view * SEQL * ATT;
    const int row0 = blockIdx.x * 64;
    sgemm_tf32_64x128(A + (size_t)row0 * HID, HID, W, ATT, bias,
                      O + (size_t)row0 * ATT, ATT, HID, mul);
}

// ---------------------------------------------------------------------------
// Kernel 2: fused flash attention on tensor cores.
//   grid (16 q-tiles of 128 rows, 8 views), 512 threads = 16 warps.
//   streams 64-key K/V/bias tiles.  Two register accumulators:
//     oacc = online-softmax(QK^T) @ V    (rescaled; normalized at end)
//     bacc = attn_bias @ V               (plain)
//   x = oacc/l + bacc, stored transposed into g_x[S][V*A].
// ---------------------------------------------------------------------------
#define BQ    128
#define BK    64
#define LDQ   132     // Q/K row stride
#define LDV   136     // V row stride (tig*8+g conflict-free)
#define LDS2  68      // S / bias row stride
#define SMEM_ATTN_FLOATS (BQ*LDQ + BK*LDQ + BK*LDV + BQ*LDS2 + BQ*LDS2 + 3*BQ)
#define SMEM_ATTN_BYTES  (SMEM_ATTN_FLOATS * 4)

__global__ void __launch_bounds__(512, 1) attn_kernel(const float* __restrict__ attn_bias)
{
    extern __shared__ float sm[];
    float* Qs   = sm;                       // [BQ][LDQ]
    float* Ks   = Qs  + BQ * LDQ;           // [BK][LDQ]
    float* Vs   = Ks  + BK * LDQ;           // [BK][LDV]
    float* Ssm  = Vs  + BK * LDV;           // [BQ][LDS2]
    float* Bsm  = Ssm + BQ * LDS2;          // [BQ][LDS2]
    float* mrow = Bsm + BQ * LDS2;
    float* lrow = mrow + BQ;
    float* crow = lrow + BQ;

    const int tid  = threadIdx.x;
    const int wid  = tid >> 5;
    const int lane = tid & 31;
    const int g    = lane >> 2;
    const int tig  = lane & 3;

    const int view = blockIdx.y;
    const int q0   = blockIdx.x * BQ;

    const float* qh = g_qh + (size_t)view * SEQL * ATT;
    const float* kh = g_kh + (size_t)view * SEQL * ATT;
    const float* vh = g_vh + (size_t)view * SEQL * ATT;
    const float* ab = attn_bias + (size_t)view * SEQL * SEQL + (size_t)q0 * SEQL;

    // load Q tile (128x128) once, tf32-rounded
    for (int i = tid; i < BQ * 32; i += 512) {
        const int r = i >> 5, c4 = (i & 31) << 2;
        *(float4*)&Qs[r * LDQ + c4] =
            tf32r4(*(const float4*)&qh[(size_t)(q0 + r) * ATT + c4]);
    }
    if (tid < BQ) { mrow[tid] = -3.0e38f; lrow[tid] = 0.f; }

    // warp tiling
    const int m0  = (wid & 7) * 16;     // row tile (phase1 & phase3)
    const int n0s = (wid >> 3) * 32;    // S col tile (phase1)
    const int n0  = (wid >> 3) * 64;    // O col tile (phase3)

    float oacc[8][4], bacc[8][4];
#pragma unroll
    for (int nt = 0; nt < 8; nt++)
#pragma unroll
        for (int i = 0; i < 4; i++) { oacc[nt][i] = 0.f; bacc[nt][i] = 0.f; }

    __syncthreads();

    for (int kt = 0; kt < SEQL / BK; kt++) {
        // ---- load K, V (tf32), bias (tf32) tiles ----
        const float* kbase = kh + (size_t)(kt * BK) * ATT;
        const float* vbase = vh + (size_t)(kt * BK) * ATT;
        for (int i = tid; i < BK * 32; i += 512) {
            const int r = i >> 5, c4 = (i & 31) << 2;
            *(float4*)&Ks[r * LDQ + c4] =
                tf32r4(*(const float4*)&kbase[(size_t)r * ATT + c4]);
            *(float4*)&Vs[r * LDV + c4] =
                tf32r4(*(const float4*)&vbase[(size_t)r * ATT + c4]);
        }
        for (int i = tid; i < BQ * 16; i += 512) {
            const int r = i >> 4, c4 = (i & 15) << 2;
            *(float4*)&Bsm[r * LDS2 + c4] =
                tf32r4(*(const float4*)&ab[(size_t)r * SEQL + kt * BK + c4]);
        }
        __syncthreads();

        // ---- phase 1: S(128x64) = Q @ K^T  (warp: 16 x 32) ----
        {
            float sacc[4][4];
#pragma unroll
            for (int nt = 0; nt < 4; nt++)
#pragma unroll
                for (int i = 0; i < 4; i++) sacc[nt][i] = 0.f;

#pragma unroll
            for (int kk = 0; kk < ATT; kk += 8) {
                const uint32_t a0 = lduf(&Qs[(m0 + g)     * LDQ + kk + tig]);
                const uint32_t a1 = lduf(&Qs[(m0 + g + 8) * LDQ + kk + tig]);
                const uint32_t a2 = lduf(&Qs[(m0 + g)     * LDQ + kk + tig + 4]);
                const uint32_t a3 = lduf(&Qs[(m0 + g + 8) * LDQ + kk + tig + 4]);
#pragma unroll
                for (int nt = 0; nt < 4; nt++) {
                    const int nr = n0s + nt * 8 + g;    // key row index
                    const uint32_t b0 = lduf(&Ks[nr * LDQ + kk + tig]);
                    const uint32_t b1 = lduf(&Ks[nr * LDQ + kk + tig + 4]);
                    mma_tf32(sacc[nt], a0, a1, a2, a3, b0, b1);
                }
            }
#pragma unroll
            for (int nt = 0; nt < 4; nt++) {
                const int col = n0s + nt * 8 + tig * 2;
                *(float2*)&Ssm[(m0 + g)     * LDS2 + col] = make_float2(sacc[nt][0], sacc[nt][1]);
                *(float2*)&Ssm[(m0 + g + 8) * LDS2 + col] = make_float2(sacc[nt][2], sacc[nt][3]);
            }
        }
        __syncthreads();

        // ---- phase 2: online softmax update (4 lanes per row) ----
        {
            const int row = tid >> 2, l4 = tid & 3, cb = l4 * 16;
            float lm = -3.0e38f;
#pragma unroll
            for (int c = 0; c < 16; c++) lm = fmaxf(lm, Ssm[row * LDS2 + cb + c]);
            lm = fmaxf(lm, __shfl_xor_sync(0xffffffffu, lm, 1));
            lm = fmaxf(lm, __shfl_xor_sync(0xffffffffu, lm, 2));
            const float mold = mrow[row];
            const float mnew = fmaxf(mold, lm);
            float ls = 0.f;
#pragma unroll
            for (int c = 0; c < 16; c++) {
                const float e = __expf(Ssm[row * LDS2 + cb + c] - mnew);
                Ssm[row * LDS2 + cb + c] = tf32r(e);
                ls += e;
            }
            ls += __shfl_xor_sync(0xffffffffu, ls, 1);
            ls += __shfl_xor_sync(0xffffffffu, ls, 2);
            if (l4 == 0) {
                const float corr = __expf(mold - mnew);
                crow[row] = corr;
                mrow[row] = mnew;
                lrow[row] = lrow[row] * corr + ls;
            }
        }
        __syncthreads();

        // ---- phase 3: oacc = oacc*corr + P@V ;  bacc += B@V  (warp 16x64) ----
        {
            const float ca = crow[m0 + g];
            const float cb2 = crow[m0 + g + 8];
#pragma unroll
            for (int nt = 0; nt < 8; nt++) {
                oacc[nt][0] *= ca;  oacc[nt][1] *= ca;
                oacc[nt][2] *= cb2; oacc[nt][3] *= cb2;
            }
#pragma unroll
            for (int ks = 0; ks < BK; ks += 8) {
                const uint32_t pa0 = lduf(&Ssm[(m0 + g)     * LDS2 + ks + tig]);
                const uint32_t pa1 = lduf(&Ssm[(m0 + g + 8) * LDS2 + ks + tig]);
                const uint32_t pa2 = lduf(&Ssm[(m0 + g)     * LDS2 + ks + tig + 4]);
                const uint32_t pa3 = lduf(&Ssm[(m0 + g + 8) * LDS2 + ks + tig + 4]);
                const uint32_t ba0 = lduf(&Bsm[(m0 + g)     * LDS2 + ks + tig]);
                const uint32_t ba1 = lduf(&Bsm[(m0 + g + 8) * LDS2 + ks + tig]);
                const uint32_t ba2 = lduf(&Bsm[(m0 + g)     * LDS2 + ks + tig + 4]);
                const uint32_t ba3 = lduf(&Bsm[(m0 + g + 8) * LDS2 + ks + tig + 4]);
#pragma unroll
                for (int nt = 0; nt < 8; nt++) {
                    const int nc = n0 + nt * 8 + g;
                    const uint32_t b0 = lduf(&Vs[(ks + tig)     * LDV + nc]);
                    const uint32_t b1 = lduf(&Vs[(ks + tig + 4) * LDV + nc]);
                    mma_tf32(oacc[nt], pa0, pa1, pa2, pa3, b0, b1);
                    mma_tf32(bacc[nt], ba0, ba1, ba2, ba3, b0, b1);
                }
            }
        }
        __syncthreads();
    }

    // ---- epilogue: x = oacc/l + bacc, stored transposed [S, V*A] ----
    const float inv0 = 1.f / lrow[m0 + g];
    const float inv1 = 1.f / lrow[m0 + g + 8];
    float* xr0 = g_x + (size_t)(q0 + m0 + g)     * HID + view * ATT;
    float* xr1 = g_x + (size_t)(q0 + m0 + g + 8) * HID + view * ATT;
#pragma unroll
    for (int nt = 0; nt < 8; nt++) {
        const int col = n0 + nt * 8 + tig * 2;
        float2 o0, o1;
        o0.x = oacc[nt][0] * inv0 + bacc[nt][0];
        o0.y = oacc[nt][1] * inv0 + bacc[nt][1];
        o1.x = oacc[nt][2] * inv1 + bacc[nt][2];
        o1.y = oacc[nt][3] * inv1 + bacc[nt][3];
        *(float2*)&xr0[col] = o0;
        *(float2*)&xr1[col] = o1;
    }
}

// ---------------------------------------------------------------------------
// Kernel 3: out = x @ wo + bo.   grid (32 Mtiles, 8 Ntiles)
// ---------------------------------------------------------------------------
__global__ void __launch_bounds__(256) out_kernel(
    const float* __restrict__ wo, const float* __restrict__ bo,
    float* __restrict__ out)
{
    const int row0 = blockIdx.x * 64;
    const int col0 = blockIdx.y * 128;
    sgemm_tf32_64x128(g_x + (size_t)row0 * HID, HID,
                      wo + col0, HID, bo + col0,
                      out + (size_t)row0 * HID + col0, HID, HID, 1.0f);
}

// ---------------------------------------------------------------------------
extern "C" void kernel_launch(void* const* d_in, const int* in_sizes, int n_in,
                              void* d_out, int out_size)
{
    const float* q  = (const float*)d_in[0];
    const float* k  = (const float*)d_in[1];
    const float* v  = (const float*)d_in[2];
    const float* ab = (const float*)d_in[3];
    const float* wq = (const float*)d_in[4];
    const float* bq = (const float*)d_in[5];
    const float* wk = (const float*)d_in[6];
    const float* bk = (const float*)d_in[7];
    const float* wv = (const float*)d_in[8];
    const float* bv = (const float*)d_in[9];
    const float* wo = (const float*)d_in[10];
    const float* bo = (const float*)d_in[11];
    float* out = (float*)d_out;

    cudaFuncSetAttribute(attn_kernel, cudaFuncAttributeMaxDynamicSharedMemorySize,
                         SMEM_ATTN_BYTES);

    proj_kernel<<<dim3(SEQL / 64, VIEWS, 3), 256>>>(q, k, v, wq, bq, wk, bk, wv, bv);
    attn_kernel<<<dim3(SEQL / BQ, VIEWS), 512, SMEM_ATTN_BYTES>>>(ab);
    out_kernel<<<dim3(SEQL / 64, HID / 128), 256>>>(wo, bo, out);
}

// round 6
// speedup vs baseline: 4.4571x; 1.1297x over previous
#include <cuda_runtime.h>
#include <math.h>
#include <stdint.h>

#define VIEWS 8
#define SEQL  2048
#define HID   1024
#define ATT   128
#define SCALE 0.08838834764831845f   /* 1/sqrt(128) */

// ---------------- scratch (device globals: no allocations allowed) ----------
__device__ float g_qh[VIEWS * SEQL * ATT];   // tf32-rounded
__device__ float g_kh[VIEWS * SEQL * ATT];   // tf32-rounded
__device__ float g_vh[VIEWS * SEQL * ATT];   // tf32-rounded
__device__ float g_x [SEQL * HID];           // x transposed to [S, V*A]
__device__ float g_zero[ATT];                // zero bias

// ---------------------------------------------------------------------------
// TF32 helpers
// ---------------------------------------------------------------------------
__device__ __forceinline__ float tf32r(float x) {
    uint32_t u;
    asm("cvt.rna.tf32.f32 %0, %1;" : "=r"(u) : "f"(x));
    return __uint_as_float(u);
}
__device__ __forceinline__ float4 tf32r4(float4 t) {
    t.x = tf32r(t.x); t.y = tf32r(t.y); t.z = tf32r(t.z); t.w = tf32r(t.w);
    return t;
}

// d += A(16x8,row) * B(8x8,col)   tf32 inputs, fp32 accum
__device__ __forceinline__ void mma_tf32(float* d,
    uint32_t a0, uint32_t a1, uint32_t a2, uint32_t a3,
    uint32_t b0, uint32_t b1)
{
    asm volatile(
        "mma.sync.aligned.m16n8k8.row.col.f32.tf32.tf32.f32 "
        "{%0,%1,%2,%3},{%4,%5,%6,%7},{%8,%9},{%0,%1,%2,%3};\n"
        : "+f"(d[0]), "+f"(d[1]), "+f"(d[2]), "+f"(d[3])
        : "r"(a0), "r"(a1), "r"(a2), "r"(a3), "r"(b0), "r"(b1));
}

__device__ __forceinline__ uint32_t lduf(const float* p) {
    return __float_as_uint(*p);
}

// ============================================================================
// TF32 tensor-core SGEMM, 64x128 output tile, 256 threads (8 warps),
// register-prefetch double-buffered global loads.
// C = (A@B + bias) * mul.   A:[..,lda] rm (pre-offset), B:[Ktot,ldb] rm.
// Warp tile: 16(m) x 64(n).  BK = 32.
// ============================================================================
#define GLDA 36     // As row stride (pad)
#define GLDB 136    // Bs row stride (pad)

__device__ __forceinline__ void sgemm_tf32_64x128(
    const float* __restrict__ A, int lda,
    const float* __restrict__ B, int ldb,
    const float* __restrict__ bias,
    float* __restrict__ C, int ldc,
    int Ktot, float mul, bool round_out)
{
    __shared__ float As[64 * GLDA];
    __shared__ float Bs[32 * GLDB];

    const int tid  = threadIdx.x;
    const int wid  = tid >> 5;
    const int lane = tid & 31;
    const int g    = lane >> 2;     // groupID
    const int tig  = lane & 3;      // thread in group

    const int m0 = (wid & 3) * 16;
    const int n0 = (wid >> 2) * 64;

    // per-thread load coordinates
    const int ar  = tid >> 3;         // A rows: ar, ar+32
    const int ac4 = (tid & 7) * 4;
    const int br  = tid >> 5;         // B rows: br + i*8
    const int bc4 = (tid & 31) * 4;

    float acc[8][4];
#pragma unroll
    for (int nt = 0; nt < 8; nt++)
#pragma unroll
        for (int i = 0; i < 4; i++) acc[nt][i] = 0.f;

    // prefetch first tiles
    float4 pa[2], pb[4];
#pragma unroll
    for (int i = 0; i < 2; i++)
        pa[i] = *(const float4*)&A[(size_t)(ar + i * 32) * lda + ac4];
#pragma unroll
    for (int i = 0; i < 4; i++)
        pb[i] = *(const float4*)&B[(size_t)(br + i * 8) * ldb + bc4];

    for (int k0 = 0; k0 < Ktot; k0 += 32) {
        // store prefetched tiles (tf32-rounded)
#pragma unroll
        for (int i = 0; i < 2; i++) {
            const float4 t = tf32r4(pa[i]);
            const int r = ar + i * 32;
            As[r * GLDA + ac4 + 0] = t.x; As[r * GLDA + ac4 + 1] = t.y;
            As[r * GLDA + ac4 + 2] = t.z; As[r * GLDA + ac4 + 3] = t.w;
        }
#pragma unroll
        for (int i = 0; i < 4; i++)
            *(float4*)&Bs[(br + i * 8) * GLDB + bc4] = tf32r4(pb[i]);
        __syncthreads();

        // issue next tile's global loads (latency hidden behind MMAs)
        if (k0 + 32 < Ktot) {
#pragma unroll
            for (int i = 0; i < 2; i++)
                pa[i] = *(const float4*)&A[(size_t)(ar + i * 32) * lda + k0 + 32 + ac4];
#pragma unroll
            for (int i = 0; i < 4; i++)
                pb[i] = *(const float4*)&B[(size_t)(k0 + 32 + br + i * 8) * ldb + bc4];
        }

#pragma unroll
        for (int kk = 0; kk < 32; kk += 8) {
            const uint32_t a0 = lduf(&As[(m0 + g)     * GLDA + kk + tig]);
            const uint32_t a1 = lduf(&As[(m0 + g + 8) * GLDA + kk + tig]);
            const uint32_t a2 = lduf(&As[(m0 + g)     * GLDA + kk + tig + 4]);
            const uint32_t a3 = lduf(&As[(m0 + g + 8) * GLDA + kk + tig + 4]);
#pragma unroll
            for (int nt = 0; nt < 8; nt++) {
                const int nc = n0 + nt * 8 + g;
                const uint32_t b0 = lduf(&Bs[(kk + tig)     * GLDB + nc]);
                const uint32_t b1 = lduf(&Bs[(kk + tig + 4) * GLDB + nc]);
                mma_tf32(acc[nt], a0, a1, a2, a3, b0, b1);
            }
        }
        __syncthreads();
    }

    // epilogue
#pragma unroll
    for (int nt = 0; nt < 8; nt++) {
        const int col = n0 + nt * 8 + tig * 2;
        const float b0 = bias[col], b1 = bias[col + 1];
        float2 o0, o1;
        o0.x = (acc[nt][0] + b0) * mul;  o0.y = (acc[nt][1] + b1) * mul;
        o1.x = (acc[nt][2] + b0) * mul;  o1.y = (acc[nt][3] + b1) * mul;
        if (round_out) {
            o0.x = tf32r(o0.x); o0.y = tf32r(o0.y);
            o1.x = tf32r(o1.x); o1.y = tf32r(o1.y);
        }
        *(float2*)&C[(size_t)(m0 + g)     * ldc + col] = o0;
        *(float2*)&C[(size_t)(m0 + g + 8) * ldc + col] = o1;
    }
}

// ---------------------------------------------------------------------------
// Kernel 1: fused QKV projection.  grid (32 Mtiles, 8 views, 3 proj)
// Outputs stored tf32-rounded so downstream kernels skip cvt.
// ---------------------------------------------------------------------------
__global__ void __launch_bounds__(256) proj_kernel(
    const float* __restrict__ q, const float* __restrict__ k,
    const float* __restrict__ v,
    const float* __restrict__ wq, const float* __restrict__ bq,
    const float* __restrict__ wk, const float* __restrict__ bk,
    const float* __restrict__ wv, const float* __restrict__ bv)
{
    const int view = blockIdx.y;
    const int pz   = blockIdx.z;
    const float *A, *W, *bias;
    float* O;
    float mul = 1.0f;
    if (pz == 0)      { A = q; W = wq; bias = bq; O = g_qh; mul = SCALE; }
    else if (pz == 1) { A = k; W = wk; bias = bk; O = g_kh; }
    else              { A = v; W = wv; bias = bv; O = g_vh; }

    A += (size_t)view * SEQL * HID;
    O += (size_t)view * SEQL * ATT;
    const int row0 = blockIdx.x * 64;
    sgemm_tf32_64x128(A + (size_t)row0 * HID, HID, W, ATT, bias,
                      O + (size_t)row0 * ATT, ATT, HID, mul, true);
}

// ---------------------------------------------------------------------------
// Kernel 1b: bias GEMM.  g_x[q][v*A+a] = attn_bias[v,q,:] @ vh[v,:,a]
// grid (32 Mtiles, 8 views).  Streams the 128MB bias tensor once.
// ---------------------------------------------------------------------------
__global__ void __launch_bounds__(256) biasv_kernel(const float* __restrict__ attn_bias)
{
    const int view = blockIdx.y;
    const int row0 = blockIdx.x * 64;
    const float* A = attn_bias + (size_t)view * SEQL * SEQL + (size_t)row0 * SEQL;
    const float* B = g_vh + (size_t)view * SEQL * ATT;
    float* C = g_x + (size_t)row0 * HID + view * ATT;
    sgemm_tf32_64x128(A, SEQL, B, ATT, g_zero, C, HID, SEQL, 1.0f, false);
}

// ---------------------------------------------------------------------------
// Kernel 2: fused flash attention on tensor cores.
//   grid (16 q-tiles of 128 rows, 8 views), 512 threads = 16 warps.
//   K/V tiles register-prefetched (already tf32).  Epilogue adds into g_x
//   (which holds the bias@V term from biasv_kernel).
// ---------------------------------------------------------------------------
#define BQ    128
#define BK    64
#define LDQ   132     // Q/K row stride
#define LDV   136     // V row stride
#define LDS2  68      // S row stride
#define SMEM_ATTN_FLOATS (BQ*LDQ + BK*LDQ + BK*LDV + BQ*LDS2 + 3*BQ)
#define SMEM_ATTN_BYTES  (SMEM_ATTN_FLOATS * 4)

__global__ void __launch_bounds__(512, 1) attn_kernel()
{
    extern __shared__ float sm[];
    float* Qs   = sm;                       // [BQ][LDQ]
    float* Ks   = Qs  + BQ * LDQ;           // [BK][LDQ]
    float* Vs   = Ks  + BK * LDQ;           // [BK][LDV]
    float* Ssm  = Vs  + BK * LDV;           // [BQ][LDS2]
    float* mrow = Ssm + BQ * LDS2;
    float* lrow = mrow + BQ;
    float* crow = lrow + BQ;

    const int tid  = threadIdx.x;
    const int wid  = tid >> 5;
    const int lane = tid & 31;
    const int g    = lane >> 2;
    const int tig  = lane & 3;

    const int view = blockIdx.y;
    const int q0   = blockIdx.x * BQ;

    const float* qh = g_qh + (size_t)view * SEQL * ATT;
    const float* kh = g_kh + (size_t)view * SEQL * ATT;
    const float* vh = g_vh + (size_t)view * SEQL * ATT;

    // load Q tile (128x128) once — already tf32
    for (int i = tid; i < BQ * 32; i += 512) {
        const int r = i >> 5, c4 = (i & 31) << 2;
        *(float4*)&Qs[r * LDQ + c4] = *(const float4*)&qh[(size_t)(q0 + r) * ATT + c4];
    }
    if (tid < BQ) { mrow[tid] = -3.0e38f; lrow[tid] = 0.f; }

    // per-thread K/V staging coordinates (BK*32 float4 over 512 threads = 4 each)
    const int kr0 = tid >> 3;            // rows kr0 + i*... : idx = tid + i*512
    (void)kr0;

    // warp tiling
    const int m0  = (wid & 7) * 16;     // row tile
    const int n0s = (wid >> 3) * 32;    // S col tile (phase1)
    const int n0  = (wid >> 3) * 64;    // O col tile (phase3)

    float oacc[8][4];
#pragma unroll
    for (int nt = 0; nt < 8; nt++)
#pragma unroll
        for (int i = 0; i < 4; i++) oacc[nt][i] = 0.f;

    // prefetch first K/V tile into registers
    float4 pk[4], pv[4];
#pragma unroll
    for (int i = 0; i < 4; i++) {
        const int idx = tid + i * 512;
        const int r = idx >> 5, c4 = (idx & 31) << 2;
        pk[i] = *(const float4*)&kh[(size_t)r * ATT + c4];
        pv[i] = *(const float4*)&vh[(size_t)r * ATT + c4];
    }

    __syncthreads();

    for (int kt = 0; kt < SEQL / BK; kt++) {
        // ---- commit prefetched K/V tile to smem (raw: already tf32) ----
#pragma unroll
        for (int i = 0; i < 4; i++) {
            const int idx = tid + i * 512;
            const int r = idx >> 5, c4 = (idx & 31) << 2;
            *(float4*)&Ks[r * LDQ + c4] = pk[i];
            *(float4*)&Vs[r * LDV + c4] = pv[i];
        }
        __syncthreads();

        // ---- issue next tile's global loads (hidden behind phases 1-3) ----
        if (kt + 1 < SEQL / BK) {
            const float* kbase = kh + (size_t)((kt + 1) * BK) * ATT;
            const float* vbase = vh + (size_t)((kt + 1) * BK) * ATT;
#pragma unroll
            for (int i = 0; i < 4; i++) {
                const int idx = tid + i * 512;
                const int r = idx >> 5, c4 = (idx & 31) << 2;
                pk[i] = *(const float4*)&kbase[(size_t)r * ATT + c4];
                pv[i] = *(const float4*)&vbase[(size_t)r * ATT + c4];
            }
        }

        // ---- phase 1: S(128x64) = Q @ K^T  (warp: 16 x 32) ----
        {
            float sacc[4][4];
#pragma unroll
            for (int nt = 0; nt < 4; nt++)
#pragma unroll
                for (int i = 0; i < 4; i++) sacc[nt][i] = 0.f;

#pragma unroll
            for (int kk = 0; kk < ATT; kk += 8) {
                const uint32_t a0 = lduf(&Qs[(m0 + g)     * LDQ + kk + tig]);
                const uint32_t a1 = lduf(&Qs[(m0 + g + 8) * LDQ + kk + tig]);
                const uint32_t a2 = lduf(&Qs[(m0 + g)     * LDQ + kk + tig + 4]);
                const uint32_t a3 = lduf(&Qs[(m0 + g + 8) * LDQ + kk + tig + 4]);
#pragma unroll
                for (int nt = 0; nt < 4; nt++) {
                    const int nr = n0s + nt * 8 + g;
                    const uint32_t b0 = lduf(&Ks[nr * LDQ + kk + tig]);
                    const uint32_t b1 = lduf(&Ks[nr * LDQ + kk + tig + 4]);
                    mma_tf32(sacc[nt], a0, a1, a2, a3, b0, b1);
                }
            }
#pragma unroll
            for (int nt = 0; nt < 4; nt++) {
                const int col = n0s + nt * 8 + tig * 2;
                *(float2*)&Ssm[(m0 + g)     * LDS2 + col] = make_float2(sacc[nt][0], sacc[nt][1]);
                *(float2*)&Ssm[(m0 + g + 8) * LDS2 + col] = make_float2(sacc[nt][2], sacc[nt][3]);
            }
        }
        __syncthreads();

        // ---- phase 2: online softmax update (4 lanes per row) ----
        {
            const int row = tid >> 2, l4 = tid & 3, cb = l4 * 16;
            float lm = -3.0e38f;
#pragma unroll
            for (int c = 0; c < 16; c++) lm = fmaxf(lm, Ssm[row * LDS2 + cb + c]);
            lm = fmaxf(lm, __shfl_xor_sync(0xffffffffu, lm, 1));
            lm = fmaxf(lm, __shfl_xor_sync(0xffffffffu, lm, 2));
            const float mold = mrow[row];
            const float mnew = fmaxf(mold, lm);
            float ls = 0.f;
#pragma unroll
            for (int c = 0; c < 16; c++) {
                const float e = __expf(Ssm[row * LDS2 + cb + c] - mnew);
                Ssm[row * LDS2 + cb + c] = tf32r(e);
                ls += e;
            }
            ls += __shfl_xor_sync(0xffffffffu, ls, 1);
            ls += __shfl_xor_sync(0xffffffffu, ls, 2);
            if (l4 == 0) {
                const float corr = __expf(mold - mnew);
                crow[row] = corr;
                mrow[row] = mnew;
                lrow[row] = lrow[row] * corr + ls;
            }
        }
        __syncthreads();

        // ---- phase 3: oacc = oacc*corr + P@V  (warp 16x64) ----
        {
            const float ca  = crow[m0 + g];
            const float cb2 = crow[m0 + g + 8];
#pragma unroll
            for (int nt = 0; nt < 8; nt++) {
                oacc[nt][0] *= ca;  oacc[nt][1] *= ca;
                oacc[nt][2] *= cb2; oacc[nt][3] *= cb2;
            }
#pragma unroll
            for (int ks = 0; ks < BK; ks += 8) {
                const uint32_t pa0 = lduf(&Ssm[(m0 + g)     * LDS2 + ks + tig]);
                const uint32_t pa1 = lduf(&Ssm[(m0 + g + 8) * LDS2 + ks + tig]);
                const uint32_t pa2 = lduf(&Ssm[(m0 + g)     * LDS2 + ks + tig + 4]);
                const uint32_t pa3 = lduf(&Ssm[(m0 + g + 8) * LDS2 + ks + tig + 4]);
#pragma unroll
                for (int nt = 0; nt < 8; nt++) {
                    const int nc = n0 + nt * 8 + g;
                    const uint32_t b0 = lduf(&Vs[(ks + tig)     * LDV + nc]);
                    const uint32_t b1 = lduf(&Vs[(ks + tig + 4) * LDV + nc]);
                    mma_tf32(oacc[nt], pa0, pa1, pa2, pa3, b0, b1);
                }
            }
        }
        __syncthreads();
    }

    // ---- epilogue: g_x += oacc/l  (g_x holds bias@V term) ----
    const float inv0 = 1.f / lrow[m0 + g];
    const float inv1 = 1.f / lrow[m0 + g + 8];
    float* xr0 = g_x + (size_t)(q0 + m0 + g)     * HID + view * ATT;
    float* xr1 = g_x + (size_t)(q0 + m0 + g + 8) * HID + view * ATT;
#pragma unroll
    for (int nt = 0; nt < 8; nt++) {
        const int col = n0 + nt * 8 + tig * 2;
        float2 x0 = *(const float2*)&xr0[col];
        float2 x1 = *(const float2*)&xr1[col];
        x0.x += oacc[nt][0] * inv0;  x0.y += oacc[nt][1] * inv0;
        x1.x += oacc[nt][2] * inv1;  x1.y += oacc[nt][3] * inv1;
        *(float2*)&xr0[col] = x0;
        *(float2*)&xr1[col] = x1;
    }
}

// ---------------------------------------------------------------------------
// Kernel 3: out = x @ wo + bo.   grid (32 Mtiles, 8 Ntiles)
// ---------------------------------------------------------------------------
__global__ void __launch_bounds__(256) out_kernel(
    const float* __restrict__ wo, const float* __restrict__ bo,
    float* __restrict__ out)
{
    const int row0 = blockIdx.x * 64;
    const int col0 = blockIdx.y * 128;
    sgemm_tf32_64x128(g_x + (size_t)row0 * HID, HID,
                      wo + col0, HID, bo + col0,
                      out + (size_t)row0 * HID + col0, HID, HID, 1.0f, false);
}

// ---------------------------------------------------------------------------
extern "C" void kernel_launch(void* const* d_in, const int* in_sizes, int n_in,
                              void* d_out, int out_size)
{
    const float* q  = (const float*)d_in[0];
    const float* k  = (const float*)d_in[1];
    const float* v  = (const float*)d_in[2];
    const float* ab = (const float*)d_in[3];
    const float* wq = (const float*)d_in[4];
    const float* bq = (const float*)d_in[5];
    const float* wk = (const float*)d_in[6];
    const float* bk = (const float*)d_in[7];
    const float* wv = (const float*)d_in[8];
    const float* bv = (const float*)d_in[9];
    const float* wo = (const float*)d_in[10];
    const float* bo = (const float*)d_in[11];
    float* out = (float*)d_out;

    cudaFuncSetAttribute(attn_kernel, cudaFuncAttributeMaxDynamicSharedMemorySize,
                         SMEM_ATTN_BYTES);

    proj_kernel<<<dim3(SEQL / 64, VIEWS, 3), 256>>>(q, k, v, wq, bq, wk, bk, wv, bv);
    biasv_kernel<<<dim3(SEQL / 64, VIEWS), 256>>>(ab);
    attn_kernel<<<dim3(SEQL / BQ, VIEWS), 512, SMEM_ATTN_BYTES>>>();
    out_kernel<<<dim3(SEQL / 64, HID / 128), 256>>>(wo, bo, out);
}

// round 8
// speedup vs baseline: 5.4839x; 1.2304x over previous
#include <cuda_runtime.h>
#include <math.h>
#include <stdint.h>

#define VIEWS 8
#define SEQL  2048
#define HID   1024
#define ATT   128
#define SCALE 0.08838834764831845f   /* 1/sqrt(128) */

// ---------------- scratch (device globals: no allocations allowed) ----------
__device__ float g_qh[VIEWS * SEQL * ATT];   // tf32-rounded
__device__ float g_kh[VIEWS * SEQL * ATT];   // tf32-rounded
__device__ float g_vh[VIEWS * SEQL * ATT];   // tf32-rounded
__device__ float g_x [SEQL * HID];           // x transposed to [S, V*A]
__device__ float g_zero[ATT];                // zero bias

// ---------------------------------------------------------------------------
// helpers
// ---------------------------------------------------------------------------
__device__ __forceinline__ float tf32r(float x) {
    uint32_t u;
    asm("cvt.rna.tf32.f32 %0, %1;" : "=r"(u) : "f"(x));
    return __uint_as_float(u);
}
__device__ __forceinline__ float4 tf32r4(float4 t) {
    t.x = tf32r(t.x); t.y = tf32r(t.y); t.z = tf32r(t.z); t.w = tf32r(t.w);
    return t;
}

__device__ __forceinline__ void mma_tf32(float* d,
    uint32_t a0, uint32_t a1, uint32_t a2, uint32_t a3,
    uint32_t b0, uint32_t b1)
{
    asm volatile(
        "mma.sync.aligned.m16n8k8.row.col.f32.tf32.tf32.f32 "
        "{%0,%1,%2,%3},{%4,%5,%6,%7},{%8,%9},{%0,%1,%2,%3};\n"
        : "+f"(d[0]), "+f"(d[1]), "+f"(d[2]), "+f"(d[3])
        : "r"(a0), "r"(a1), "r"(a2), "r"(a3), "r"(b0), "r"(b1));
}

__device__ __forceinline__ uint32_t lduf(const float* p) {
    return __float_as_uint(*p);
}

__device__ __forceinline__ uint32_t smem_u32(const void* p) {
    uint32_t a;
    asm("{ .reg .u64 t; cvta.to.shared.u64 t, %1; cvt.u32.u64 %0, t; }"
        : "=r"(a) : "l"(p));
    return a;
}
__device__ __forceinline__ void cpasync16(uint32_t dst, const void* src) {
    asm volatile("cp.async.cg.shared.global [%0], [%1], 16;\n" :: "r"(dst), "l"(src));
}
#define CP_COMMIT() asm volatile("cp.async.commit_group;\n" ::: "memory")
#define CP_WAIT0()  asm volatile("cp.async.wait_group 0;\n"  ::: "memory")

// ============================================================================
// TF32 tensor-core GEMM, 128x128 block tile, 256 threads (8 warps, 4m x 2n),
// warp tile 32x64, BK=32, register-prefetch double-buffered global loads.
// C = (A@B + bias) * mul.
// ============================================================================
#define GLDA 36     // As row stride (pad)
#define GLDB 136    // Bs row stride (pad)

__device__ __forceinline__ void sgemm_tf32_128x128(
    const float* __restrict__ A, int lda,
    const float* __restrict__ B, int ldb,
    const float* __restrict__ bias,
    float* __restrict__ C, int ldc,
    int Ktot, float mul, bool round_out)
{
    __shared__ float As[128 * GLDA];
    __shared__ float Bs[32 * GLDB];

    const int tid  = threadIdx.x;
    const int wid  = tid >> 5;
    const int lane = tid & 31;
    const int g    = lane >> 2;
    const int tig  = lane & 3;

    const int m0 = (wid & 3) * 32;
    const int n0 = (wid >> 2) * 64;

    float acc[2][8][4];
#pragma unroll
    for (int mt = 0; mt < 2; mt++)
#pragma unroll
        for (int nt = 0; nt < 8; nt++)
#pragma unroll
            for (int i = 0; i < 4; i++) acc[mt][nt][i] = 0.f;

    // prefetch first tiles (A:128x32 -> 4 f4/thread, B:32x128 -> 4 f4/thread)
    float4 pa[4], pb[4];
#pragma unroll
    for (int i = 0; i < 4; i++) {
        const int ia = tid + i * 256;
        pa[i] = *(const float4*)&A[(size_t)(ia >> 3) * lda + ((ia & 7) << 2)];
        pb[i] = *(const float4*)&B[(size_t)(ia >> 5) * ldb + ((ia & 31) << 2)];
    }

    for (int k0 = 0; k0 < Ktot; k0 += 32) {
        // commit prefetched tiles (tf32-rounded)
#pragma unroll
        for (int i = 0; i < 4; i++) {
            const int ia = tid + i * 256;
            *(float4*)&As[(ia >> 3) * GLDA + ((ia & 7) << 2)]  = tf32r4(pa[i]);
            *(float4*)&Bs[(ia >> 5) * GLDB + ((ia & 31) << 2)] = tf32r4(pb[i]);
        }
        __syncthreads();

        if (k0 + 32 < Ktot) {
#pragma unroll
            for (int i = 0; i < 4; i++) {
                const int ia = tid + i * 256;
                pa[i] = *(const float4*)&A[(size_t)(ia >> 3) * lda + k0 + 32 + ((ia & 7) << 2)];
                pb[i] = *(const float4*)&B[(size_t)(k0 + 32 + (ia >> 5)) * ldb + ((ia & 31) << 2)];
            }
        }

#pragma unroll
        for (int kk = 0; kk < 32; kk += 8) {
            uint32_t a[2][4];
#pragma unroll
            for (int mt = 0; mt < 2; mt++) {
                const int r = m0 + mt * 16;
                a[mt][0] = lduf(&As[(r + g)     * GLDA + kk + tig]);
                a[mt][1] = lduf(&As[(r + g + 8) * GLDA + kk + tig]);
                a[mt][2] = lduf(&As[(r + g)     * GLDA + kk + tig + 4]);
                a[mt][3] = lduf(&As[(r + g + 8) * GLDA + kk + tig + 4]);
            }
#pragma unroll
            for (int nt = 0; nt < 8; nt++) {
                const int nc = n0 + nt * 8 + g;
                const uint32_t b0 = lduf(&Bs[(kk + tig)     * GLDB + nc]);
                const uint32_t b1 = lduf(&Bs[(kk + tig + 4) * GLDB + nc]);
                mma_tf32(acc[0][nt], a[0][0], a[0][1], a[0][2], a[0][3], b0, b1);
                mma_tf32(acc[1][nt], a[1][0], a[1][1], a[1][2], a[1][3], b0, b1);
            }
        }
        __syncthreads();
    }

    // epilogue
#pragma unroll
    for (int mt = 0; mt < 2; mt++) {
        const int r = m0 + mt * 16;
#pragma unroll
        for (int nt = 0; nt < 8; nt++) {
            const int col = n0 + nt * 8 + tig * 2;
            const float b0 = bias[col], b1 = bias[col + 1];
            float2 o0, o1;
            o0.x = (acc[mt][nt][0] + b0) * mul;  o0.y = (acc[mt][nt][1] + b1) * mul;
            o1.x = (acc[mt][nt][2] + b0) * mul;  o1.y = (acc[mt][nt][3] + b1) * mul;
            if (round_out) {
                o0.x = tf32r(o0.x); o0.y = tf32r(o0.y);
                o1.x = tf32r(o1.x); o1.y = tf32r(o1.y);
            }
            *(float2*)&C[(size_t)(r + g)     * ldc + col] = o0;
            *(float2*)&C[(size_t)(r + g + 8) * ldc + col] = o1;
        }
    }
}

// ---------------------------------------------------------------------------
// Kernel 1: fused QKV projection.  grid (16 Mtiles, 8 views, 3 proj)
// ---------------------------------------------------------------------------
__global__ void __launch_bounds__(256) proj_kernel(
    const float* __restrict__ q, const float* __restrict__ k,
    const float* __restrict__ v,
    const float* __restrict__ wq, const float* __restrict__ bq,
    const float* __restrict__ wk, const float* __restrict__ bk,
    const float* __restrict__ wv, const float* __restrict__ bv)
{
    const int view = blockIdx.y;
    const int pz   = blockIdx.z;
    const float *A, *W, *bias;
    float* O;
    float mul = 1.0f;
    if (pz == 0)      { A = q; W = wq; bias = bq; O = g_qh; mul = SCALE; }
    else if (pz == 1) { A = k; W = wk; bias = bk; O = g_kh; }
    else              { A = v; W = wv; bias = bv; O = g_vh; }

    A += (size_t)view * SEQL * HID;
    O += (size_t)view * SEQL * ATT;
    const int row0 = blockIdx.x * 128;
    sgemm_tf32_128x128(A + (size_t)row0 * HID, HID, W, ATT, bias,
                       O + (size_t)row0 * ATT, ATT, HID, mul, true);
}

// ---------------------------------------------------------------------------
// Kernel 1b: bias GEMM.  g_x[q][v*A+a] = attn_bias[v,q,:] @ vh[v,:,a]
// grid (16 Mtiles, 8 views)
// ---------------------------------------------------------------------------
__global__ void __launch_bounds__(256) biasv_kernel(const float* __restrict__ attn_bias)
{
    const int view = blockIdx.y;
    const int row0 = blockIdx.x * 128;
    const float* A = attn_bias + (size_t)view * SEQL * SEQL + (size_t)row0 * SEQL;
    const float* B = g_vh + (size_t)view * SEQL * ATT;
    float* C = g_x + (size_t)row0 * HID + view * ATT;
    sgemm_tf32_128x128(A, SEQL, B, ATT, g_zero, C, HID, SEQL, 1.0f, false);
}

// ---------------------------------------------------------------------------
// Kernel 2: FA2-style attention, register softmax, 128 threads (4 warps),
//   BQ=64, BK=64, grid (32 q-tiles, 8 views) = 256 CTAs (2 resident/SM).
//   Each warp owns 16 full S-rows; softmax entirely in registers + shfl.
//   P (S-MMA D frags) -> A frags for P@V via 8-shfl register transpose.
//   Epilogue: g_x += oacc/l  (g_x already holds bias@V from biasv_kernel).
// ---------------------------------------------------------------------------
#define BQ    64
#define BK    64
#define NT_KT (SEQL / BK)
#define LDQ   132     // Q/K row stride
#define LDV   136     // V row stride
#define SMEM_ATTN_FLOATS (BQ * LDQ + BK * LDQ + BK * LDV)
#define SMEM_ATTN_BYTES  (SMEM_ATTN_FLOATS * 4)

__global__ void __launch_bounds__(128) attn_kernel()
{
    extern __shared__ float sm[];
    float* Qs = sm;                 // [BQ][LDQ]
    float* Ks = Qs + BQ * LDQ;      // [BK][LDQ]
    float* Vs = Ks + BK * LDQ;      // [BK][LDV]

    const int tid  = threadIdx.x;
    const int wid  = tid >> 5;
    const int lane = tid & 31;
    const int g    = lane >> 2;
    const int tig  = lane & 3;

    const int view = blockIdx.y;
    const int q0   = blockIdx.x * BQ;

    const float* qh = g_qh + (size_t)view * SEQL * ATT + (size_t)q0 * ATT;
    const float* kh = g_kh + (size_t)view * SEQL * ATT;
    const float* vh = g_vh + (size_t)view * SEQL * ATT;

    const uint32_t sQ = smem_u32(Qs);
    const uint32_t sK = smem_u32(Ks);
    const uint32_t sV = smem_u32(Vs);

    // ---- stage Q (once) + K/V tile 0 via cp.async ----
    // 64x128 floats = 2048 float4 / 128 threads = 16 per thread
#pragma unroll
    for (int i = 0; i < 16; i++) {
        const int idx = tid + i * 128;
        const int r = idx >> 5, c4 = (idx & 31) << 2;
        cpasync16(sQ + (r * LDQ + c4) * 4, &qh[(size_t)r * ATT + c4]);
        cpasync16(sK + (r * LDQ + c4) * 4, &kh[(size_t)r * ATT + c4]);
        cpasync16(sV + (r * LDV + c4) * 4, &vh[(size_t)r * ATT + c4]);
    }
    CP_COMMIT();

    const int m0 = wid * 16;        // warp's S-row block

    float oacc[16][4];
#pragma unroll
    for (int nt = 0; nt < 16; nt++)
#pragma unroll
        for (int i = 0; i < 4; i++) oacc[nt][i] = 0.f;

    float mst0 = -3.0e38f, mst1 = -3.0e38f;   // row-max state (rows g, g+8)
    float lst0 = 0.f,      lst1 = 0.f;        // row-sum state

    const int srcA = (g << 2) + (tig >> 1);   // shfl source for P col tig
    const int srcB = srcA + 2;                // shfl source for P col tig+4
    const bool odd = (tig & 1);

    CP_WAIT0();
    __syncthreads();

    for (int kt = 0; kt < NT_KT; kt++) {
        // ---- phase 1: S(16x64 per warp) = Q @ K^T ----
        float sacc[8][4];
#pragma unroll
        for (int j = 0; j < 8; j++)
#pragma unroll
            for (int i = 0; i < 4; i++) sacc[j][i] = 0.f;

#pragma unroll
        for (int kk = 0; kk < ATT; kk += 8) {
            const uint32_t a0 = lduf(&Qs[(m0 + g)     * LDQ + kk + tig]);
            const uint32_t a1 = lduf(&Qs[(m0 + g + 8) * LDQ + kk + tig]);
            const uint32_t a2 = lduf(&Qs[(m0 + g)     * LDQ + kk + tig + 4]);
            const uint32_t a3 = lduf(&Qs[(m0 + g + 8) * LDQ + kk + tig + 4]);
#pragma unroll
            for (int j = 0; j < 8; j++) {
                const int nr = j * 8 + g;
                const uint32_t b0 = lduf(&Ks[nr * LDQ + kk + tig]);
                const uint32_t b1 = lduf(&Ks[nr * LDQ + kk + tig + 4]);
                mma_tf32(sacc[j], a0, a1, a2, a3, b0, b1);
            }
        }

        // ---- phase 2: register online softmax ----
        {
            float mx0 = -3.0e38f, mx1 = -3.0e38f;
#pragma unroll
            for (int j = 0; j < 8; j++) {
                mx0 = fmaxf(mx0, fmaxf(sacc[j][0], sacc[j][1]));
                mx1 = fmaxf(mx1, fmaxf(sacc[j][2], sacc[j][3]));
            }
            mx0 = fmaxf(mx0, __shfl_xor_sync(0xffffffffu, mx0, 1));
            mx0 = fmaxf(mx0, __shfl_xor_sync(0xffffffffu, mx0, 2));
            mx1 = fmaxf(mx1, __shfl_xor_sync(0xffffffffu, mx1, 1));
            mx1 = fmaxf(mx1, __shfl_xor_sync(0xffffffffu, mx1, 2));

            const float mnew0 = fmaxf(mst0, mx0);
            const float mnew1 = fmaxf(mst1, mx1);
            const float corr0 = __expf(mst0 - mnew0);
            const float corr1 = __expf(mst1 - mnew1);
            mst0 = mnew0; mst1 = mnew1;

            float s0 = 0.f, s1 = 0.f;
#pragma unroll
            for (int j = 0; j < 8; j++) {
                float e;
                e = __expf(sacc[j][0] - mnew0); s0 += e; sacc[j][0] = tf32r(e);
                e = __expf(sacc[j][1] - mnew0); s0 += e; sacc[j][1] = tf32r(e);
                e = __expf(sacc[j][2] - mnew1); s1 += e; sacc[j][2] = tf32r(e);
                e = __expf(sacc[j][3] - mnew1); s1 += e; sacc[j][3] = tf32r(e);
            }
            s0 += __shfl_xor_sync(0xffffffffu, s0, 1);
            s0 += __shfl_xor_sync(0xffffffffu, s0, 2);
            s1 += __shfl_xor_sync(0xffffffffu, s1, 1);
            s1 += __shfl_xor_sync(0xffffffffu, s1, 2);
            lst0 = lst0 * corr0 + s0;
            lst1 = lst1 * corr1 + s1;

#pragma unroll
            for (int nt = 0; nt < 16; nt++) {
                oacc[nt][0] *= corr0; oacc[nt][1] *= corr0;
                oacc[nt][2] *= corr1; oacc[nt][3] *= corr1;
            }
        }

        // ---- phase 3: oacc += P @ V  (P from regs via shfl transpose) ----
#pragma unroll
        for (int jk = 0; jk < 8; jk++) {
            // A frags: a0=(row g,col tig) a1=(row g+8,col tig)
            //          a2=(row g,col tig+4) a3=(row g+8,col tig+4)
            const float e0 = __shfl_sync(0xffffffffu, sacc[jk][0], srcA);
            const float e1 = __shfl_sync(0xffffffffu, sacc[jk][1], srcA);
            const float f0 = __shfl_sync(0xffffffffu, sacc[jk][2], srcA);
            const float f1 = __shfl_sync(0xffffffffu, sacc[jk][3], srcA);
            const float e2 = __shfl_sync(0xffffffffu, sacc[jk][0], srcB);
            const float e3 = __shfl_sync(0xffffffffu, sacc[jk][1], srcB);
            const float f2 = __shfl_sync(0xffffffffu, sacc[jk][2], srcB);
            const float f3 = __shfl_sync(0xffffffffu, sacc[jk][3], srcB);
            const uint32_t a0 = __float_as_uint(odd ? e1 : e0);
            const uint32_t a1 = __float_as_uint(odd ? f1 : f0);
            const uint32_t a2 = __float_as_uint(odd ? e3 : e2);
            const uint32_t a3 = __float_as_uint(odd ? f3 : f2);
#pragma unroll
            for (int nt = 0; nt < 16; nt++) {
                const int nc = nt * 8 + g;
                const uint32_t b0 = lduf(&Vs[(jk * 8 + tig)     * LDV + nc]);
                const uint32_t b1 = lduf(&Vs[(jk * 8 + tig + 4) * LDV + nc]);
                mma_tf32(oacc[nt], a0, a1, a2, a3, b0, b1);
            }
        }

        __syncthreads();   // all warps done with Ks/Vs

        if (kt + 1 < NT_KT) {
            const float* kb = kh + (size_t)((kt + 1) * BK) * ATT;
            const float* vb = vh + (size_t)((kt + 1) * BK) * ATT;
#pragma unroll
            for (int i = 0; i < 16; i++) {
                const int idx = tid + i * 128;
                const int r = idx >> 5, c4 = (idx & 31) << 2;
                cpasync16(sK + (r * LDQ + c4) * 4, &kb[(size_t)r * ATT + c4]);
                cpasync16(sV + (r * LDV + c4) * 4, &vb[(size_t)r * ATT + c4]);
            }
            CP_COMMIT();
            CP_WAIT0();
        }
        __syncthreads();   // buffer refilled
    }

    // ---- epilogue: g_x += oacc / l ----
    const float inv0 = 1.f / lst0;
    const float inv1 = 1.f / lst1;
    float* xr0 = g_x + (size_t)(q0 + m0 + g)     * HID + view * ATT;
    float* xr1 = g_x + (size_t)(q0 + m0 + g + 8) * HID + view * ATT;
#pragma unroll
    for (int nt = 0; nt < 16; nt++) {
        const int col = nt * 8 + tig * 2;
        float2 x0 = *(const float2*)&xr0[col];
        float2 x1 = *(const float2*)&xr1[col];
        x0.x += oacc[nt][0] * inv0;  x0.y += oacc[nt][1] * inv0;
        x1.x += oacc[nt][2] * inv1;  x1.y += oacc[nt][3] * inv1;
        *(float2*)&xr0[col] = x0;
        *(float2*)&xr1[col] = x1;
    }
}

// ---------------------------------------------------------------------------
// Kernel 3: out = x @ wo + bo.   grid (16 Mtiles, 8 Ntiles)
// ---------------------------------------------------------------------------
__global__ void __launch_bounds__(256) out_kernel(
    const float* __restrict__ wo, const float* __restrict__ bo,
    float* __restrict__ out)
{
    const int row0 = blockIdx.x * 128;
    const int col0 = blockIdx.y * 128;
    sgemm_tf32_128x128(g_x + (size_t)row0 * HID, HID,
                       wo + col0, HID, bo + col0,
                       out + (size_t)row0 * HID + col0, HID, HID, 1.0f, false);
}

// ---------------------------------------------------------------------------
extern "C" void kernel_launch(void* const* d_in, const int* in_sizes, int n_in,
                              void* d_out, int out_size)
{
    const float* q  = (const float*)d_in[0];
    const float* k  = (const float*)d_in[1];
    const float* v  = (const float*)d_in[2];
    const float* ab = (const float*)d_in[3];
    const float* wq = (const float*)d_in[4];
    const float* bq = (const float*)d_in[5];
    const float* wk = (const float*)d_in[6];
    const float* bk = (const float*)d_in[7];
    const float* wv = (const float*)d_in[8];
    const float* bv = (const float*)d_in[9];
    const float* wo = (const float*)d_in[10];
    const float* bo = (const float*)d_in[11];
    float* out = (float*)d_out;

    cudaFuncSetAttribute(attn_kernel, cudaFuncAttributeMaxDynamicSharedMemorySize,
                         SMEM_ATTN_BYTES);

    proj_kernel<<<dim3(SEQL / 128, VIEWS, 3), 256>>>(q, k, v, wq, bq, wk, bk, wv, bv);
    biasv_kernel<<<dim3(SEQL / 128, VIEWS), 256>>>(ab);
    attn_kernel<<<dim3(SEQL / BQ, VIEWS), 128, SMEM_ATTN_BYTES>>>();
    out_kernel<<<dim3(SEQL / 128, HID / 128), 256>>>(wo, bo, out);
}

// round 10
// speedup vs baseline: 5.6919x; 1.0379x over previous
#include <cuda_runtime.h>
#include <math.h>
#include <stdint.h>

#define VIEWS 8
#define SEQL  2048
#define HID   1024
#define ATT   128
#define SCALE 0.08838834764831845f   /* 1/sqrt(128) */

// ---------------- scratch (device globals: no allocations allowed) ----------
__device__ float g_qh[VIEWS * SEQL * ATT];   // tf32-rounded
__device__ float g_kh[VIEWS * SEQL * ATT];   // tf32-rounded
__device__ float g_vh[VIEWS * SEQL * ATT];   // tf32-rounded
__device__ float g_x [SEQL * HID];           // x transposed to [S, V*A]
__device__ float g_zero[ATT];                // zero bias

// ---------------------------------------------------------------------------
// helpers
// ---------------------------------------------------------------------------
__device__ __forceinline__ float tf32r(float x) {
    uint32_t u;
    asm("cvt.rna.tf32.f32 %0, %1;" : "=r"(u) : "f"(x));
    return __uint_as_float(u);
}

__device__ __forceinline__ void mma_tf32(float* d,
    uint32_t a0, uint32_t a1, uint32_t a2, uint32_t a3,
    uint32_t b0, uint32_t b1)
{
    asm volatile(
        "mma.sync.aligned.m16n8k8.row.col.f32.tf32.tf32.f32 "
        "{%0,%1,%2,%3},{%4,%5,%6,%7},{%8,%9},{%0,%1,%2,%3};\n"
        : "+f"(d[0]), "+f"(d[1]), "+f"(d[2]), "+f"(d[3])
        : "r"(a0), "r"(a1), "r"(a2), "r"(a3), "r"(b0), "r"(b1));
}

__device__ __forceinline__ uint32_t lduf(const float* p) {
    return __float_as_uint(*p);
}

__device__ __forceinline__ uint32_t smem_u32(const void* p) {
    uint32_t a;
    asm("{ .reg .u64 t; cvta.to.shared.u64 t, %1; cvt.u32.u64 %0, t; }"
        : "=r"(a) : "l"(p));
    return a;
}
__device__ __forceinline__ void cpasync16(uint32_t dst, const void* src) {
    asm volatile("cp.async.cg.shared.global [%0], [%1], 16;\n" :: "r"(dst), "l"(src));
}
#define CP_COMMIT() asm volatile("cp.async.commit_group;\n" ::: "memory")
#define CP_WAIT0()  asm volatile("cp.async.wait_group 0;\n"  ::: "memory")
#define CP_WAIT1()  asm volatile("cp.async.wait_group 1;\n"  ::: "memory")

// ============================================================================
// TF32 tensor-core GEMM, 128x128 block, 256 threads (8 warps, 4m x 2n),
// warp tile 32x64, BK=32, 3-stage cp.async smem pipeline.
// TF32 rounding applied at fragment load when the operand isn't pre-rounded.
// C = (A@B + bias) * mul.
// ============================================================================
#define GLDA 36     // As row stride (pad)
#define GLDB 136    // Bs row stride (pad)
#define STG_F (128 * GLDA + 32 * GLDB)          // floats per stage = 8960
#define SMEM_GEMM_BYTES (3 * STG_F * 4)         // 107520 B

template<bool RA, bool RB>
__device__ __forceinline__ void sgemm_pipe(
    const float* __restrict__ A, int lda,
    const float* __restrict__ B, int ldb,
    const float* __restrict__ bias,
    float* __restrict__ C, int ldc,
    int Ktot, float mul, bool round_out)
{
    extern __shared__ float dynsm[];

    const int tid  = threadIdx.x;
    const int wid  = tid >> 5;
    const int lane = tid & 31;
    const int g    = lane >> 2;
    const int tig  = lane & 3;

    const int m0 = (wid & 3) * 32;
    const int n0 = (wid >> 2) * 64;

    const int ar  = tid >> 3, ac4 = (tid & 7) << 2;
    const int br  = tid >> 5, bc4 = (tid & 31) << 2;

    const int niter = Ktot >> 5;

    auto issue = [&](int it) {
        const int k0 = it << 5;
        float* As = dynsm + (it % 3) * STG_F;
        float* Bs = As + 128 * GLDA;
        const uint32_t sA = smem_u32(As), sB = smem_u32(Bs);
#pragma unroll
        for (int i = 0; i < 4; i++) {
            const int r  = ar + i * 32;
            cpasync16(sA + (uint32_t)(r * GLDA + ac4) * 4,
                      &A[(size_t)r * lda + k0 + ac4]);
            const int rb = br + i * 8;
            cpasync16(sB + (uint32_t)(rb * GLDB + bc4) * 4,
                      &B[(size_t)(k0 + rb) * ldb + bc4]);
        }
        CP_COMMIT();
    };

    float acc[2][8][4];
#pragma unroll
    for (int mt = 0; mt < 2; mt++)
#pragma unroll
        for (int nt = 0; nt < 8; nt++)
#pragma unroll
            for (int i = 0; i < 4; i++) acc[mt][nt][i] = 0.f;

    issue(0);
    if (niter > 1) issue(1);

    for (int it = 0; it < niter; it++) {
        if (it + 1 < niter) CP_WAIT1(); else CP_WAIT0();
        __syncthreads();
        if (it + 2 < niter) issue(it + 2);

        const float* As = dynsm + (it % 3) * STG_F;
        const float* Bs = As + 128 * GLDA;

#pragma unroll
        for (int kk = 0; kk < 32; kk += 8) {
            uint32_t a[2][4];
#pragma unroll
            for (int mt = 0; mt < 2; mt++) {
                const int r = m0 + mt * 16;
                float x0 = As[(r + g)     * GLDA + kk + tig];
                float x1 = As[(r + g + 8) * GLDA + kk + tig];
                float x2 = As[(r + g)     * GLDA + kk + tig + 4];
                float x3 = As[(r + g + 8) * GLDA + kk + tig + 4];
                if (RA) { x0 = tf32r(x0); x1 = tf32r(x1); x2 = tf32r(x2); x3 = tf32r(x3); }
                a[mt][0] = __float_as_uint(x0);
                a[mt][1] = __float_as_uint(x1);
                a[mt][2] = __float_as_uint(x2);
                a[mt][3] = __float_as_uint(x3);
            }
#pragma unroll
            for (int nt = 0; nt < 8; nt++) {
                const int nc = n0 + nt * 8 + g;
                float y0 = Bs[(kk + tig)     * GLDB + nc];
                float y1 = Bs[(kk + tig + 4) * GLDB + nc];
                if (RB) { y0 = tf32r(y0); y1 = tf32r(y1); }
                const uint32_t b0 = __float_as_uint(y0);
                const uint32_t b1 = __float_as_uint(y1);
                mma_tf32(acc[0][nt], a[0][0], a[0][1], a[0][2], a[0][3], b0, b1);
                mma_tf32(acc[1][nt], a[1][0], a[1][1], a[1][2], a[1][3], b0, b1);
            }
        }
    }

    // epilogue
#pragma unroll
    for (int mt = 0; mt < 2; mt++) {
        const int r = m0 + mt * 16;
#pragma unroll
        for (int nt = 0; nt < 8; nt++) {
            const int col = n0 + nt * 8 + tig * 2;
            const float b0 = bias[col], b1 = bias[col + 1];
            float2 o0, o1;
            o0.x = (acc[mt][nt][0] + b0) * mul;  o0.y = (acc[mt][nt][1] + b1) * mul;
            o1.x = (acc[mt][nt][2] + b0) * mul;  o1.y = (acc[mt][nt][3] + b1) * mul;
            if (round_out) {
                o0.x = tf32r(o0.x); o0.y = tf32r(o0.y);
                o1.x = tf32r(o1.x); o1.y = tf32r(o1.y);
            }
            *(float2*)&C[(size_t)(r + g)     * ldc + col] = o0;
            *(float2*)&C[(size_t)(r + g + 8) * ldc + col] = o1;
        }
    }
}

// ---------------------------------------------------------------------------
// Kernel 1: fused QKV projection.  grid (16 Mtiles, 8 views, 3 proj)
// ---------------------------------------------------------------------------
__global__ void __launch_bounds__(256, 2) proj_kernel(
    const float* __restrict__ q, const float* __restrict__ k,
    const float* __restrict__ v,
    const float* __restrict__ wq, const float* __restrict__ bq,
    const float* __restrict__ wk, const float* __restrict__ bk,
    const float* __restrict__ wv, const float* __restrict__ bv)
{
    const int view = blockIdx.y;
    const int pz   = blockIdx.z;
    const float *A, *W, *bias;
    float* O;
    float mul = 1.0f;
    if (pz == 0)      { A = q; W = wq; bias = bq; O = g_qh; mul = SCALE; }
    else if (pz == 1) { A = k; W = wk; bias = bk; O = g_kh; }
    else              { A = v; W = wv; bias = bv; O = g_vh; }

    A += (size_t)view * SEQL * HID;
    O += (size_t)view * SEQL * ATT;
    const int row0 = blockIdx.x * 128;
    sgemm_pipe<true, true>(A + (size_t)row0 * HID, HID, W, ATT, bias,
                           O + (size_t)row0 * ATT, ATT, HID, mul, true);
}

// ---------------------------------------------------------------------------
// Kernel 1b: bias GEMM.  g_x[q][v*A+a] = attn_bias[v,q,:] @ vh[v,:,a]
// grid (16 Mtiles, 8 views).  B (g_vh) is pre-rounded -> no cvt.
// ---------------------------------------------------------------------------
__global__ void __launch_bounds__(256, 2) biasv_kernel(const float* __restrict__ attn_bias)
{
    const int view = blockIdx.y;
    const int row0 = blockIdx.x * 128;
    const float* A = attn_bias + (size_t)view * SEQL * SEQL + (size_t)row0 * SEQL;
    const float* B = g_vh + (size_t)view * SEQL * ATT;
    float* C = g_x + (size_t)row0 * HID + view * ATT;
    sgemm_pipe<true, false>(A, SEQL, B, ATT, g_zero, C, HID, SEQL, 1.0f, false);
}

// ---------------------------------------------------------------------------
// Kernel 2: FA2-style attention, register softmax, 128 threads (4 warps),
//   BQ=64, BK=32, double-buffered cp.async K/V pipeline,
//   grid (32 q-tiles, 8 views) = 256 CTAs, 2 resident/SM (smem 100KB).
// ---------------------------------------------------------------------------
#define BQ    64
#define BK    32
#define NT_KT (SEQL / BK)    // 64
#define LDQ   132
#define LDV   136
#define KSTG  (BK * LDQ)     // 4224 floats
#define VSTG  (BK * LDV)     // 4352 floats
#define SMEM_ATTN_FLOATS (BQ * LDQ + 2 * KSTG + 2 * VSTG)   // 25600
#define SMEM_ATTN_BYTES  (SMEM_ATTN_FLOATS * 4)             // 102400

__global__ void __launch_bounds__(128) attn_kernel()
{
    extern __shared__ float sm[];
    float* Qs = sm;                          // [BQ][LDQ]
    float* Kb = Qs + BQ * LDQ;               // [2][BK][LDQ]
    float* Vb = Kb + 2 * KSTG;               // [2][BK][LDV]

    const int tid  = threadIdx.x;
    const int wid  = tid >> 5;
    const int lane = tid & 31;
    const int g    = lane >> 2;
    const int tig  = lane & 3;

    const int view = blockIdx.y;
    const int q0   = blockIdx.x * BQ;

    const float* qh = g_qh + (size_t)view * SEQL * ATT + (size_t)q0 * ATT;
    const float* kh = g_kh + (size_t)view * SEQL * ATT;
    const float* vh = g_vh + (size_t)view * SEQL * ATT;

    const uint32_t sQ = smem_u32(Qs);
    const uint32_t sK = smem_u32(Kb);
    const uint32_t sV = smem_u32(Vb);

    auto issueKV = [&](int it) {
        const int buf = it & 1;
        const float* kbase = kh + (size_t)(it * BK) * ATT;
        const float* vbase = vh + (size_t)(it * BK) * ATT;
#pragma unroll
        for (int i = 0; i < 8; i++) {
            const int idx = tid + i * 128;             // 0..1023
            const int r = idx >> 5, c4 = (idx & 31) << 2;
            cpasync16(sK + (uint32_t)(buf * KSTG + r * LDQ + c4) * 4,
                      &kbase[(size_t)r * ATT + c4]);
            cpasync16(sV + (uint32_t)(buf * VSTG + r * LDV + c4) * 4,
                      &vbase[(size_t)r * ATT + c4]);
        }
        CP_COMMIT();
    };

    // prologue: group0 = Q + KV(0), group1 = KV(1)
    {
#pragma unroll
        for (int i = 0; i < 16; i++) {
            const int idx = tid + i * 128;             // 0..2047
            const int r = idx >> 5, c4 = (idx & 31) << 2;
            cpasync16(sQ + (uint32_t)(r * LDQ + c4) * 4, &qh[(size_t)r * ATT + c4]);
        }
#pragma unroll
        for (int i = 0; i < 8; i++) {
            const int idx = tid + i * 128;
            const int r = idx >> 5, c4 = (idx & 31) << 2;
            cpasync16(sK + (uint32_t)(r * LDQ + c4) * 4, &kh[(size_t)r * ATT + c4]);
            cpasync16(sV + (uint32_t)(r * LDV + c4) * 4, &vh[(size_t)r * ATT + c4]);
        }
        CP_COMMIT();
        issueKV(1);
    }

    const int m0 = wid * 16;

    float oacc[16][4];
#pragma unroll
    for (int nt = 0; nt < 16; nt++)
#pragma unroll
        for (int i = 0; i < 4; i++) oacc[nt][i] = 0.f;

    float mst0 = -3.0e38f, mst1 = -3.0e38f;
    float lst0 = 0.f,      lst1 = 0.f;

    const int srcA = (g << 2) + (tig >> 1);
    const int srcB = srcA + 2;
    const bool odd = (tig & 1);

    for (int kt = 0; kt < NT_KT; kt++) {
        if (kt + 1 < NT_KT) CP_WAIT1(); else CP_WAIT0();
        __syncthreads();

        const float* Ks = Kb + (kt & 1) * KSTG;
        const float* Vs = Vb + (kt & 1) * VSTG;

        // ---- phase 1: S(16x32 per warp) = Q @ K^T ----
        float sacc[4][4];
#pragma unroll
        for (int j = 0; j < 4; j++)
#pragma unroll
            for (int i = 0; i < 4; i++) sacc[j][i] = 0.f;

#pragma unroll
        for (int kk = 0; kk < ATT; kk += 8) {
            const uint32_t a0 = lduf(&Qs[(m0 + g)     * LDQ + kk + tig]);
            const uint32_t a1 = lduf(&Qs[(m0 + g + 8) * LDQ + kk + tig]);
            const uint32_t a2 = lduf(&Qs[(m0 + g)     * LDQ + kk + tig + 4]);
            const uint32_t a3 = lduf(&Qs[(m0 + g + 8) * LDQ + kk + tig + 4]);
#pragma unroll
            for (int j = 0; j < 4; j++) {
                const int nr = j * 8 + g;
                const uint32_t b0 = lduf(&Ks[nr * LDQ + kk + tig]);
                const uint32_t b1 = lduf(&Ks[nr * LDQ + kk + tig + 4]);
                mma_tf32(sacc[j], a0, a1, a2, a3, b0, b1);
            }
        }

        // ---- phase 2: register online softmax ----
        {
            float mx0 = -3.0e38f, mx1 = -3.0e38f;
#pragma unroll
            for (int j = 0; j < 4; j++) {
                mx0 = fmaxf(mx0, fmaxf(sacc[j][0], sacc[j][1]));
                mx1 = fmaxf(mx1, fmaxf(sacc[j][2], sacc[j][3]));
            }
            mx0 = fmaxf(mx0, __shfl_xor_sync(0xffffffffu, mx0, 1));
            mx0 = fmaxf(mx0, __shfl_xor_sync(0xffffffffu, mx0, 2));
            mx1 = fmaxf(mx1, __shfl_xor_sync(0xffffffffu, mx1, 1));
            mx1 = fmaxf(mx1, __shfl_xor_sync(0xffffffffu, mx1, 2));

            const float mnew0 = fmaxf(mst0, mx0);
            const float mnew1 = fmaxf(mst1, mx1);
            const float corr0 = __expf(mst0 - mnew0);
            const float corr1 = __expf(mst1 - mnew1);
            mst0 = mnew0; mst1 = mnew1;

            float s0 = 0.f, s1 = 0.f;
#pragma unroll
            for (int j = 0; j < 4; j++) {
                float e;
                e = __expf(sacc[j][0] - mnew0); s0 += e; sacc[j][0] = tf32r(e);
                e = __expf(sacc[j][1] - mnew0); s0 += e; sacc[j][1] = tf32r(e);
                e = __expf(sacc[j][2] - mnew1); s1 += e; sacc[j][2] = tf32r(e);
                e = __expf(sacc[j][3] - mnew1); s1 += e; sacc[j][3] = tf32r(e);
            }
            s0 += __shfl_xor_sync(0xffffffffu, s0, 1);
            s0 += __shfl_xor_sync(0xffffffffu, s0, 2);
            s1 += __shfl_xor_sync(0xffffffffu, s1, 1);
            s1 += __shfl_xor_sync(0xffffffffu, s1, 2);
            lst0 = lst0 * corr0 + s0;
            lst1 = lst1 * corr1 + s1;

#pragma unroll
            for (int nt = 0; nt < 16; nt++) {
                oacc[nt][0] *= corr0; oacc[nt][1] *= corr0;
                oacc[nt][2] *= corr1; oacc[nt][3] *= corr1;
            }
        }

        // ---- phase 3: oacc += P @ V  (register shfl transpose) ----
#pragma unroll
        for (int jk = 0; jk < 4; jk++) {
            const float e0 = __shfl_sync(0xffffffffu, sacc[jk][0], srcA);
            const float e1 = __shfl_sync(0xffffffffu, sacc[jk][1], srcA);
            const float f0 = __shfl_sync(0xffffffffu, sacc[jk][2], srcA);
            const float f1 = __shfl_sync(0xffffffffu, sacc[jk][3], srcA);
            const float e2 = __shfl_sync(0xffffffffu, sacc[jk][0], srcB);
            const float e3 = __shfl_sync(0xffffffffu, sacc[jk][1], srcB);
            const float f2 = __shfl_sync(0xffffffffu, sacc[jk][2], srcB);
            const float f3 = __shfl_sync(0xffffffffu, sacc[jk][3], srcB);
            const uint32_t a0 = __float_as_uint(odd ? e1 : e0);
            const uint32_t a1 = __float_as_uint(odd ? f1 : f0);
            const uint32_t a2 = __float_as_uint(odd ? e3 : e2);
            const uint32_t a3 = __float_as_uint(odd ? f3 : f2);
#pragma unroll
            for (int nt = 0; nt < 16; nt++) {
                const int nc = nt * 8 + g;
                const uint32_t b0 = lduf(&Vs[(jk * 8 + tig)     * LDV + nc]);
                const uint32_t b1 = lduf(&Vs[(jk * 8 + tig + 4) * LDV + nc]);
                mma_tf32(oacc[nt], a0, a1, a2, a3, b0, b1);
            }
        }

        __syncthreads();
        if (kt + 2 < NT_KT) issueKV(kt + 2);
    }

    // ---- epilogue: g_x += oacc / l ----
    const float inv0 = 1.f / lst0;
    const float inv1 = 1.f / lst1;
    float* xr0 = g_x + (size_t)(q0 + m0 + g)     * HID + view * ATT;
    float* xr1 = g_x + (size_t)(q0 + m0 + g + 8) * HID + view * ATT;
#pragma unroll
    for (int nt = 0; nt < 16; nt++) {
        const int col = nt * 8 + tig * 2;
        float2 x0 = *(const float2*)&xr0[col];
        float2 x1 = *(const float2*)&xr1[col];
        x0.x += oacc[nt][0] * inv0;  x0.y += oacc[nt][1] * inv0;
        x1.x += oacc[nt][2] * inv1;  x1.y += oacc[nt][3] * inv1;
        *(float2*)&xr0[col] = x0;
        *(float2*)&xr1[col] = x1;
    }
}

// ---------------------------------------------------------------------------
// Kernel 3: out = x @ wo + bo.   grid (16 Mtiles, 8 Ntiles)
// ---------------------------------------------------------------------------
__global__ void __launch_bounds__(256, 2) out_kernel(
    const float* __restrict__ wo, const float* __restrict__ bo,
    float* __restrict__ out)
{
    const int row0 = blockIdx.x * 128;
    const int col0 = blockIdx.y * 128;
    sgemm_pipe<true, true>(g_x + (size_t)row0 * HID, HID,
                           wo + col0, HID, bo + col0,
                           out + (size_t)row0 * HID + col0, HID, HID, 1.0f, false);
}

// ---------------------------------------------------------------------------
extern "C" void kernel_launch(void* const* d_in, const int* in_sizes, int n_in,
                              void* d_out, int out_size)
{
    const float* q  = (const float*)d_in[0];
    const float* k  = (const float*)d_in[1];
    const float* v  = (const float*)d_in[2];
    const float* ab = (const float*)d_in[3];
    const float* wq = (const float*)d_in[4];
    const float* bq = (const float*)d_in[5];
    const float* wk = (const float*)d_in[6];
    const float* bk = (const float*)d_in[7];
    const float* wv = (const float*)d_in[8];
    const float* bv = (const float*)d_in[9];
    const float* wo = (const float*)d_in[10];
    const float* bo = (const float*)d_in[11];
    float* out = (float*)d_out;

    cudaFuncSetAttribute(proj_kernel,  cudaFuncAttributeMaxDynamicSharedMemorySize, SMEM_GEMM_BYTES);
    cudaFuncSetAttribute(biasv_kernel, cudaFuncAttributeMaxDynamicSharedMemorySize, SMEM_GEMM_BYTES);
    cudaFuncSetAttribute(out_kernel,   cudaFuncAttributeMaxDynamicSharedMemorySize, SMEM_GEMM_BYTES);
    cudaFuncSetAttribute(attn_kernel,  cudaFuncAttributeMaxDynamicSharedMemorySize, SMEM_ATTN_BYTES);

    proj_kernel<<<dim3(SEQL / 128, VIEWS, 3), 256, SMEM_GEMM_BYTES>>>(
        q, k, v, wq, bq, wk, bk, wv, bv);
    biasv_kernel<<<dim3(SEQL / 128, VIEWS), 256, SMEM_GEMM_BYTES>>>(ab);
    attn_kernel<<<dim3(SEQL / BQ, VIEWS), 128, SMEM_ATTN_BYTES>>>();
    out_kernel<<<dim3(SEQL / 128, HID / 128), 256, SMEM_GEMM_BYTES>>>(wo, bo, out);
}